// round 2
// baseline (speedup 1.0000x reference)
#include <cuda_runtime.h>
#include <cuda_bf16.h>
#include <math.h>

// Problem constants: N=100000, E=3200000, F=128, H=32, C=2
#define MAXN 100000
#define MAXE 3200000
#define F_DIM 128
#define H_DIM 32

// Scratch (__device__ globals; cudaMalloc is forbidden)
__device__ __align__(256) float g_deg [MAXN];
__device__ __align__(256) float g_h1s [MAXN * H_DIM];   // (x@W1)*dinv[node]
__device__ __align__(256) float g_acc1[MAXN * H_DIM];   // edge accumulator (init = self-loop)
__device__ __align__(256) float g_gs  [MAXN * 2];       // (relu@W2)*dinv[node]
__device__ __align__(256) float g_acc2[MAXN * 2];

// ---------------- degree (self-loop = init 1.0) ----------------
__global__ void k_init_deg(int n) {
    int i = blockIdx.x * blockDim.x + threadIdx.x;
    if (i < n) g_deg[i] = 1.0f;
}

__global__ void k_count_deg(const int* __restrict__ ei, int E) {
    int e = blockIdx.x * blockDim.x + threadIdx.x;
    if (e < E) {
        int dst = __ldg(ei + E + e);                  // edge_index[1][e]
        atomicAdd(&g_deg[dst], 1.0f);
    }
}

// ---------------- GEMM1 + pre-scale: h1s = (x@W1)*rsqrt(deg); acc1 = h1s ----------------
__global__ void k_gemm1(const float* __restrict__ x, const float* __restrict__ W1, int n) {
    __shared__ float Ws[F_DIM * H_DIM];   // 16 KB
    __shared__ float xs[8][F_DIM];        // 4 KB
    int row0 = blockIdx.x * 8;

    for (int i = threadIdx.x; i < F_DIM * H_DIM; i += 256) Ws[i] = W1[i];
    for (int i = threadIdx.x; i < 8 * F_DIM; i += 256) {
        int r = i >> 7, k = i & 127;
        int node = row0 + r;
        xs[r][k] = (node < n) ? x[(size_t)node * F_DIM + k] : 0.0f;
    }
    __syncthreads();

    int r = threadIdx.x >> 5;        // 0..7
    int c = threadIdx.x & 31;        // 0..31
    int node = row0 + r;
    if (node >= n) return;

    float s = 0.0f;
    #pragma unroll
    for (int k = 0; k < F_DIM; k++) s = fmaf(xs[r][k], Ws[k * H_DIM + c], s);

    s *= rsqrtf(g_deg[node]);
    g_h1s [(size_t)node * H_DIM + c] = s;
    g_acc1[(size_t)node * H_DIM + c] = s;   // self-loop contribution
}

// ---------------- L1 edge aggregation: acc1[dst] += h1s[src]  (8 thr/edge, v4 RED) ----------------
__global__ void k_agg1(const int* __restrict__ ei, int E) {
    long long t = (long long)blockIdx.x * blockDim.x + threadIdx.x;
    if (t >= (long long)E * 8) return;
    int e = (int)(t >> 3);
    int k = (int)(t & 7) * 4;
    int src = __ldg(ei + e);
    int dst = __ldg(ei + E + e);
    const float4 v = *(const float4*)(g_h1s + (size_t)src * H_DIM + k);
    float* p = g_acc1 + (size_t)dst * H_DIM + k;
    asm volatile("red.global.add.v4.f32 [%0], {%1, %2, %3, %4};"
                 :: "l"(p), "f"(v.x), "f"(v.y), "f"(v.z), "f"(v.w) : "memory");
}

// ---------------- epilogue L1 + GEMM2: gs = (relu(dinv*acc1 + b1) @ W2) * dinv ----------------
__global__ void k_layer2(const float* __restrict__ b1, const float* __restrict__ W2, int n) {
    int node = (blockIdx.x * blockDim.x + threadIdx.x) >> 5;
    int lane = threadIdx.x & 31;
    if (node >= n) return;
    float di = rsqrtf(g_deg[node]);
    float t = fmaf(di, g_acc1[(size_t)node * H_DIM + lane], b1[lane]);
    t = fmaxf(t, 0.0f);
    float p0 = t * W2[lane * 2 + 0];
    float p1 = t * W2[lane * 2 + 1];
    #pragma unroll
    for (int o = 16; o > 0; o >>= 1) {
        p0 += __shfl_down_sync(0xFFFFFFFFu, p0, o);
        p1 += __shfl_down_sync(0xFFFFFFFFu, p1, o);
    }
    if (lane == 0) {
        float2 v = make_float2(p0 * di, p1 * di);
        *(float2*)(g_gs   + (size_t)node * 2) = v;   // pre-scaled message
        *(float2*)(g_acc2 + (size_t)node * 2) = v;   // self-loop contribution
    }
}

// ---------------- L2 edge aggregation: acc2[dst] += gs[src]  (1 thr/edge, v2 RED) ----------------
__global__ void k_agg2(const int* __restrict__ ei, int E) {
    int e = blockIdx.x * blockDim.x + threadIdx.x;
    if (e >= E) return;
    int src = __ldg(ei + e);
    int dst = __ldg(ei + E + e);
    const float2 v = *(const float2*)(g_gs + (size_t)src * 2);
    float* p = g_acc2 + (size_t)dst * 2;
    asm volatile("red.global.add.v2.f32 [%0], {%1, %2};"
                 :: "l"(p), "f"(v.x), "f"(v.y) : "memory");
}

// ---------------- output: logits = dinv*acc2 + b2; log_softmax ----------------
__global__ void k_out(const float* __restrict__ b2, float* __restrict__ out, int n) {
    int i = blockIdx.x * blockDim.x + threadIdx.x;
    if (i >= n) return;
    float di = rsqrtf(g_deg[i]);
    float2 a = *(const float2*)(g_acc2 + (size_t)i * 2);
    float l0 = fmaf(di, a.x, b2[0]);
    float l1 = fmaf(di, a.y, b2[1]);
    float m  = fmaxf(l0, l1);
    float lse = m + log1pf(expf(fminf(l0, l1) - m));
    ((float2*)out)[i] = make_float2(l0 - lse, l1 - lse);
}

extern "C" void kernel_launch(void* const* d_in, const int* in_sizes, int n_in,
                              void* d_out, int out_size) {
    const float* x  = (const float*)d_in[0];      // [N,128] f32
    const int*   ei = (const int*)d_in[1];        // [2,E] int32 (JAX downcasts int64 -> int32)
    const float* W1 = (const float*)d_in[2];      // [128,32]
    const float* b1 = (const float*)d_in[3];      // [32]
    const float* W2 = (const float*)d_in[4];      // [32,2]
    const float* b2 = (const float*)d_in[5];      // [2]
    float*       out = (float*)d_out;             // [N,2]

    const int N = in_sizes[0] / F_DIM;
    const int E = in_sizes[1] / 2;

    const int TB = 256;
    k_init_deg <<<(N + TB - 1) / TB, TB>>>(N);
    k_count_deg<<<(E + TB - 1) / TB, TB>>>(ei, E);
    k_gemm1<<<(N + 7) / 8, TB>>>(x, W1, N);
    long long t1 = (long long)E * 8;
    k_agg1<<<(unsigned)((t1 + TB - 1) / TB), TB>>>(ei, E);
    k_layer2<<<(N * 32 + TB - 1) / TB, TB>>>(b1, W2, N);
    k_agg2<<<(E + TB - 1) / TB, TB>>>(ei, E);
    k_out<<<(N + TB - 1) / TB, TB>>>(b2, out, N);
}

// round 5
// speedup vs baseline: 1.3754x; 1.3754x over previous
#include <cuda_runtime.h>
#include <cuda_bf16.h>
#include <math.h>

// N=100000, E=3200000, F=128, H=32, C=2
#define MAXN 100000
#define MAXE 3200000
#define F_DIM 128
#define H_DIM 32

// Scratch (__device__ globals; cudaMalloc forbidden)  ~28MB
__device__ __align__(256) int   g_degi[MAXN];        // in-degree (excl. self loop)
__device__ __align__(256) int   g_off [MAXN];        // CSR row offsets (exclusive scan)
__device__ __align__(256) int   g_cur [MAXN];        // scatter cursors
__device__ __align__(256) int   g_csr [MAXE];        // src ids grouped by dst
__device__ __align__(256) int   g_part[1024];        // scan partials
__device__ __align__(256) float g_h1s [MAXN * H_DIM];// (x@W1)*dinv[node]
__device__ __align__(256) float g_gs  [MAXN * 2];    // (relu(...)@W2)*dinv[node]

// ---------------- zero degree ----------------
__global__ void k_zero(int n) {
    int i = blockIdx.x * blockDim.x + threadIdx.x;
    if (i < n) g_degi[i] = 0;
}

// ---------------- histogram of dst ----------------
__global__ void k_hist(const int* __restrict__ ei, int E) {
    int e = blockIdx.x * blockDim.x + threadIdx.x;
    if (e < E) atomicAdd(&g_degi[__ldg(ei + E + e)], 1);
}

// ---------------- block-level exclusive scan (1024/block) ----------------
__global__ void k_scan1(int n) {
    __shared__ int wsum[32];
    int i = blockIdx.x * 1024 + threadIdx.x;
    int lane = threadIdx.x & 31, wid = threadIdx.x >> 5;
    int v = (i < n) ? g_degi[i] : 0;
    int s = v;
    #pragma unroll
    for (int o = 1; o < 32; o <<= 1) { int t = __shfl_up_sync(~0u, s, o); if (lane >= o) s += t; }
    if (lane == 31) wsum[wid] = s;
    __syncthreads();
    if (wid == 0) {
        int ws = wsum[lane];
        #pragma unroll
        for (int o = 1; o < 32; o <<= 1) { int t = __shfl_up_sync(~0u, ws, o); if (lane >= o) ws += t; }
        wsum[lane] = ws;
    }
    __syncthreads();
    int excl = s - v + (wid > 0 ? wsum[wid - 1] : 0);
    if (i < n) g_off[i] = excl;
    if (threadIdx.x == 1023) g_part[blockIdx.x] = wsum[31];   // block total (sole writer)
}

__global__ void k_scan2(int nb) {   // single block, 1024 threads
    __shared__ int wsum[32];
    int t = threadIdx.x, lane = t & 31, wid = t >> 5;
    int v = (t < nb) ? g_part[t] : 0;
    int s = v;
    #pragma unroll
    for (int o = 1; o < 32; o <<= 1) { int u = __shfl_up_sync(~0u, s, o); if (lane >= o) s += u; }
    if (lane == 31) wsum[wid] = s;
    __syncthreads();
    if (wid == 0) {
        int ws = wsum[lane];
        #pragma unroll
        for (int o = 1; o < 32; o <<= 1) { int u = __shfl_up_sync(~0u, ws, o); if (lane >= o) ws += u; }
        wsum[lane] = ws;
    }
    __syncthreads();
    int excl = s - v + (wid > 0 ? wsum[wid - 1] : 0);
    if (t < nb) g_part[t] = excl;
}

__global__ void k_scan3(int n) {
    int i = blockIdx.x * blockDim.x + threadIdx.x;
    if (i < n) {
        int o = g_off[i] + g_part[i >> 10];
        g_off[i] = o;
        g_cur[i] = o;
    }
}

// ---------------- scatter: build CSR (src grouped by dst) ----------------
__global__ void k_scatter(const int* __restrict__ ei, int E) {
    int e = blockIdx.x * blockDim.x + threadIdx.x;
    if (e < E) {
        int src = __ldg(ei + e);
        int dst = __ldg(ei + E + e);
        int pos = atomicAdd(&g_cur[dst], 1);
        g_csr[pos] = src;
    }
}

// ---------------- GEMM1: h1s = (x@W1) * rsqrt(deg)  (4x4 register tiling, K tiled in halves) ----------------
// block = 128 threads, 64 rows x 32 cols per block; smem = 16640 + 16384 = 33024 B
__global__ void k_gemm1(const float* __restrict__ x, const float* __restrict__ W1, int n) {
    __shared__ float xs[64][65];           // one K-half, pad 65: conflict-free scalar reads
    __shared__ float Ws[128][32];          // full W1
    int row0 = blockIdx.x * 64;
    int t = threadIdx.x;

    for (int i = t; i < F_DIM * H_DIM; i += 128) Ws[i >> 5][i & 31] = W1[i];

    int tx = t & 7;        // col group: cols 4*tx..4*tx+3
    int ty = t >> 3;       // row group: rows 4*ty..4*ty+3
    float acc[4][4] = {{0}};

    #pragma unroll
    for (int half = 0; half < 2; half++) {
        if (half) __syncthreads();         // protect xs before overwrite
        // load 64 rows x 64 cols of x (float4 coalesced): 1024 float4s, 8 per thread
        #pragma unroll
        for (int it = 0; it < 8; it++) {
            int idx = t + 128 * it;        // 0..1023
            int r = idx >> 4, c4 = idx & 15;
            int node = row0 + r;
            float4 v = make_float4(0.f, 0.f, 0.f, 0.f);
            if (node < n) v = *(const float4*)(x + (size_t)node * F_DIM + half * 64 + c4 * 4);
            xs[r][c4 * 4 + 0] = v.x; xs[r][c4 * 4 + 1] = v.y;
            xs[r][c4 * 4 + 2] = v.z; xs[r][c4 * 4 + 3] = v.w;
        }
        __syncthreads();

        #pragma unroll
        for (int k = 0; k < 64; k++) {
            float4 wv = *(float4*)&Ws[half * 64 + k][tx * 4];
            float x0 = xs[ty * 4 + 0][k];
            float x1 = xs[ty * 4 + 1][k];
            float x2 = xs[ty * 4 + 2][k];
            float x3 = xs[ty * 4 + 3][k];
            acc[0][0] = fmaf(x0, wv.x, acc[0][0]); acc[0][1] = fmaf(x0, wv.y, acc[0][1]);
            acc[0][2] = fmaf(x0, wv.z, acc[0][2]); acc[0][3] = fmaf(x0, wv.w, acc[0][3]);
            acc[1][0] = fmaf(x1, wv.x, acc[1][0]); acc[1][1] = fmaf(x1, wv.y, acc[1][1]);
            acc[1][2] = fmaf(x1, wv.z, acc[1][2]); acc[1][3] = fmaf(x1, wv.w, acc[1][3]);
            acc[2][0] = fmaf(x2, wv.x, acc[2][0]); acc[2][1] = fmaf(x2, wv.y, acc[2][1]);
            acc[2][2] = fmaf(x2, wv.z, acc[2][2]); acc[2][3] = fmaf(x2, wv.w, acc[2][3]);
            acc[3][0] = fmaf(x3, wv.x, acc[3][0]); acc[3][1] = fmaf(x3, wv.y, acc[3][1]);
            acc[3][2] = fmaf(x3, wv.z, acc[3][2]); acc[3][3] = fmaf(x3, wv.w, acc[3][3]);
        }
    }

    #pragma unroll
    for (int i = 0; i < 4; i++) {
        int node = row0 + ty * 4 + i;
        if (node < n) {
            float di = rsqrtf((float)(g_degi[node] + 1));
            float4 v = make_float4(acc[i][0] * di, acc[i][1] * di, acc[i][2] * di, acc[i][3] * di);
            *(float4*)(g_h1s + (size_t)node * H_DIM + tx * 4) = v;
        }
    }
}

// ---------------- fused L1 gather + ReLU + GEMM2: warp per dst ----------------
__global__ void k_agg1_l2(const float* __restrict__ b1, const float* __restrict__ W2, int n) {
    int w = (blockIdx.x * blockDim.x + threadIdx.x) >> 5;
    int lane = threadIdx.x & 31;
    if (w >= n) return;
    int base = g_off[w];
    int d = g_degi[w];
    float acc = g_h1s[(size_t)w * H_DIM + lane];     // self-loop term
    for (int i0 = 0; i0 < d; i0 += 32) {
        int s = ((i0 + lane) < d) ? __ldg(&g_csr[base + i0 + lane]) : 0;
        int m = min(32, d - i0);
        for (int j = 0; j < m; j++) {
            int src = __shfl_sync(0xffffffffu, s, j);
            acc += __ldg(&g_h1s[(size_t)src * H_DIM + lane]);
        }
    }
    float di = rsqrtf((float)(d + 1));
    float tv = fmaf(di, acc, b1[lane]);
    tv = fmaxf(tv, 0.0f);
    float p0 = tv * W2[lane * 2 + 0];
    float p1 = tv * W2[lane * 2 + 1];
    #pragma unroll
    for (int o = 16; o > 0; o >>= 1) {
        p0 += __shfl_down_sync(0xffffffffu, p0, o);
        p1 += __shfl_down_sync(0xffffffffu, p1, o);
    }
    if (lane == 0)
        *(float2*)(g_gs + (size_t)w * 2) = make_float2(p0 * di, p1 * di);
}

// ---------------- fused L2 gather + log_softmax: thread per dst ----------------
__global__ void k_agg2_out(const float* __restrict__ b2, float* __restrict__ out, int n) {
    int i = blockIdx.x * blockDim.x + threadIdx.x;
    if (i >= n) return;
    const float2* gs2 = (const float2*)g_gs;
    int base = g_off[i];
    int d = g_degi[i];
    float2 a = gs2[i];                               // self-loop term
    int j = 0;
    for (; j + 4 <= d; j += 4) {
        int s0 = __ldg(&g_csr[base + j + 0]);
        int s1 = __ldg(&g_csr[base + j + 1]);
        int s2 = __ldg(&g_csr[base + j + 2]);
        int s3 = __ldg(&g_csr[base + j + 3]);
        float2 v0 = gs2[s0], v1 = gs2[s1], v2 = gs2[s2], v3 = gs2[s3];
        a.x += v0.x + v1.x + v2.x + v3.x;
        a.y += v0.y + v1.y + v2.y + v3.y;
    }
    for (; j < d; j++) {
        float2 v = gs2[__ldg(&g_csr[base + j])];
        a.x += v.x; a.y += v.y;
    }
    float di = rsqrtf((float)(d + 1));
    float l0 = fmaf(di, a.x, b2[0]);
    float l1 = fmaf(di, a.y, b2[1]);
    float m = fmaxf(l0, l1);
    float lse = m + log1pf(expf(fminf(l0, l1) - m));
    ((float2*)out)[i] = make_float2(l0 - lse, l1 - lse);
}

extern "C" void kernel_launch(void* const* d_in, const int* in_sizes, int n_in,
                              void* d_out, int out_size) {
    const float* x  = (const float*)d_in[0];      // [N,128] f32
    const int*   ei = (const int*)d_in[1];        // [2,E] int32
    const float* W1 = (const float*)d_in[2];      // [128,32]
    const float* b1 = (const float*)d_in[3];      // [32]
    const float* W2 = (const float*)d_in[4];      // [32,2]
    const float* b2 = (const float*)d_in[5];      // [2]
    float*       out = (float*)d_out;             // [N,2]

    const int N = in_sizes[0] / F_DIM;
    const int E = in_sizes[1] / 2;
    const int TB = 256;
    const int nb = (N + 1023) / 1024;

    k_zero   <<<(N + TB - 1) / TB, TB>>>(N);
    k_hist   <<<(E + TB - 1) / TB, TB>>>(ei, E);
    k_gemm1  <<<(N + 63) / 64, 128>>>(x, W1, N);       // needs degi only
    k_scan1  <<<nb, 1024>>>(N);
    k_scan2  <<<1, 1024>>>(nb);
    k_scan3  <<<(N + TB - 1) / TB, TB>>>(N);
    k_scatter<<<(E + TB - 1) / TB, TB>>>(ei, E);
    k_agg1_l2<<<(N * 32 + TB - 1) / TB, TB>>>(b1, W2, N);
    k_agg2_out<<<(N + TB - 1) / TB, TB>>>(b2, out, N);
}

// round 6
// speedup vs baseline: 1.3915x; 1.0117x over previous
#include <cuda_runtime.h>
#include <cuda_bf16.h>
#include <math.h>

// N=100000, E=3200000, F=128, H=32, C=2
#define MAXN 100000
#define MAXE 3200000
#define F_DIM 128
#define H_DIM 32

// Scratch (__device__ globals; cudaMalloc forbidden)  ~28MB
__device__ __align__(256) int   g_degi[MAXN];        // in-degree (excl. self loop)
__device__ __align__(256) int   g_off [MAXN];        // CSR row offsets (exclusive scan)
__device__ __align__(256) int   g_cur [MAXN];        // scatter cursors
__device__ __align__(256) int   g_csr [MAXE];        // src ids grouped by dst
__device__ __align__(256) int   g_part[1024];        // scan partials
__device__ __align__(256) float g_h1s [MAXN * H_DIM];// (x@W1)*dinv[node]
__device__ __align__(256) float g_gs  [MAXN * 2];    // (relu(...)@W2)*dinv[node]

// ---------------- zero degree ----------------
__global__ void k_zero(int n) {
    int i = blockIdx.x * blockDim.x + threadIdx.x;
    if (i < n) g_degi[i] = 0;
}

// ---------------- histogram of dst ----------------
__global__ void k_hist(const int* __restrict__ ei, int E) {
    int e = blockIdx.x * blockDim.x + threadIdx.x;
    if (e < E) atomicAdd(&g_degi[__ldg(ei + E + e)], 1);
}

// ---------------- block-level exclusive scan (1024/block) ----------------
__global__ void k_scan1(int n) {
    __shared__ int wsum[32];
    int i = blockIdx.x * 1024 + threadIdx.x;
    int lane = threadIdx.x & 31, wid = threadIdx.x >> 5;
    int v = (i < n) ? g_degi[i] : 0;
    int s = v;
    #pragma unroll
    for (int o = 1; o < 32; o <<= 1) { int t = __shfl_up_sync(~0u, s, o); if (lane >= o) s += t; }
    if (lane == 31) wsum[wid] = s;
    __syncthreads();
    if (wid == 0) {
        int ws = wsum[lane];
        #pragma unroll
        for (int o = 1; o < 32; o <<= 1) { int t = __shfl_up_sync(~0u, ws, o); if (lane >= o) ws += t; }
        wsum[lane] = ws;
    }
    __syncthreads();
    int excl = s - v + (wid > 0 ? wsum[wid - 1] : 0);
    if (i < n) g_off[i] = excl;
    if (threadIdx.x == 1023) g_part[blockIdx.x] = wsum[31];   // block total (sole writer)
}

__global__ void k_scan2(int nb) {   // single block, 1024 threads
    __shared__ int wsum[32];
    int t = threadIdx.x, lane = t & 31, wid = t >> 5;
    int v = (t < nb) ? g_part[t] : 0;
    int s = v;
    #pragma unroll
    for (int o = 1; o < 32; o <<= 1) { int u = __shfl_up_sync(~0u, s, o); if (lane >= o) s += u; }
    if (lane == 31) wsum[wid] = s;
    __syncthreads();
    if (wid == 0) {
        int ws = wsum[lane];
        #pragma unroll
        for (int o = 1; o < 32; o <<= 1) { int u = __shfl_up_sync(~0u, ws, o); if (lane >= o) ws += u; }
        wsum[lane] = ws;
    }
    __syncthreads();
    int excl = s - v + (wid > 0 ? wsum[wid - 1] : 0);
    if (t < nb) g_part[t] = excl;
}

__global__ void k_scan3(int n) {
    int i = blockIdx.x * blockDim.x + threadIdx.x;
    if (i < n) {
        int o = g_off[i] + g_part[i >> 10];
        g_off[i] = o;
        g_cur[i] = o;
    }
}

// ---------------- scatter: build CSR (src grouped by dst) ----------------
__global__ void k_scatter(const int* __restrict__ ei, int E) {
    int e = blockIdx.x * blockDim.x + threadIdx.x;
    if (e < E) {
        int src = __ldg(ei + e);
        int dst = __ldg(ei + E + e);
        int pos = atomicAdd(&g_cur[dst], 1);
        g_csr[pos] = src;
    }
}

// ---------------- GEMM1: h1s = (x@W1) * rsqrt(deg)  (4x4 register tiling, K tiled in halves) ----------------
// block = 128 threads, 64 rows x 32 cols per block; smem = 16640 + 16384 = 33024 B
__global__ void k_gemm1(const float* __restrict__ x, const float* __restrict__ W1, int n) {
    __shared__ float xs[64][65];           // one K-half, pad 65: conflict-free scalar reads
    __shared__ float Ws[128][32];          // full W1
    int row0 = blockIdx.x * 64;
    int t = threadIdx.x;

    for (int i = t; i < F_DIM * H_DIM; i += 128) Ws[i >> 5][i & 31] = W1[i];

    int tx = t & 7;        // col group: cols 4*tx..4*tx+3
    int ty = t >> 3;       // row group: rows 4*ty..4*ty+3
    float acc[4][4] = {{0}};

    #pragma unroll
    for (int half = 0; half < 2; half++) {
        if (half) __syncthreads();         // protect xs before overwrite
        #pragma unroll
        for (int it = 0; it < 8; it++) {
            int idx = t + 128 * it;        // 0..1023
            int r = idx >> 4, c4 = idx & 15;
            int node = row0 + r;
            float4 v = make_float4(0.f, 0.f, 0.f, 0.f);
            if (node < n) v = *(const float4*)(x + (size_t)node * F_DIM + half * 64 + c4 * 4);
            xs[r][c4 * 4 + 0] = v.x; xs[r][c4 * 4 + 1] = v.y;
            xs[r][c4 * 4 + 2] = v.z; xs[r][c4 * 4 + 3] = v.w;
        }
        __syncthreads();

        #pragma unroll
        for (int k = 0; k < 64; k++) {
            float4 wv = *(float4*)&Ws[half * 64 + k][tx * 4];
            float x0 = xs[ty * 4 + 0][k];
            float x1 = xs[ty * 4 + 1][k];
            float x2 = xs[ty * 4 + 2][k];
            float x3 = xs[ty * 4 + 3][k];
            acc[0][0] = fmaf(x0, wv.x, acc[0][0]); acc[0][1] = fmaf(x0, wv.y, acc[0][1]);
            acc[0][2] = fmaf(x0, wv.z, acc[0][2]); acc[0][3] = fmaf(x0, wv.w, acc[0][3]);
            acc[1][0] = fmaf(x1, wv.x, acc[1][0]); acc[1][1] = fmaf(x1, wv.y, acc[1][1]);
            acc[1][2] = fmaf(x1, wv.z, acc[1][2]); acc[1][3] = fmaf(x1, wv.w, acc[1][3]);
            acc[2][0] = fmaf(x2, wv.x, acc[2][0]); acc[2][1] = fmaf(x2, wv.y, acc[2][1]);
            acc[2][2] = fmaf(x2, wv.z, acc[2][2]); acc[2][3] = fmaf(x2, wv.w, acc[2][3]);
            acc[3][0] = fmaf(x3, wv.x, acc[3][0]); acc[3][1] = fmaf(x3, wv.y, acc[3][1]);
            acc[3][2] = fmaf(x3, wv.z, acc[3][2]); acc[3][3] = fmaf(x3, wv.w, acc[3][3]);
        }
    }

    #pragma unroll
    for (int i = 0; i < 4; i++) {
        int node = row0 + ty * 4 + i;
        if (node < n) {
            float di = rsqrtf((float)(g_degi[node] + 1));
            float4 v = make_float4(acc[i][0] * di, acc[i][1] * di, acc[i][2] * di, acc[i][3] * di);
            *(float4*)(g_h1s + (size_t)node * H_DIM + tx * 4) = v;
        }
    }
}

// ---------------- fused L1 gather + ReLU + GEMM2: warp per dst, 4-way MLP unroll ----------------
__global__ void k_agg1_l2(const float* __restrict__ b1, const float* __restrict__ W2, int n) {
    int w = (blockIdx.x * blockDim.x + threadIdx.x) >> 5;
    int lane = threadIdx.x & 31;
    if (w >= n) return;
    int base = g_off[w];
    int d = g_degi[w];
    const float* __restrict__ h1 = g_h1s;
    float a0 = h1[(size_t)w * H_DIM + lane];   // self-loop term
    float a1 = 0.f, a2 = 0.f, a3 = 0.f;

    int i0 = 0;
    for (; i0 + 32 <= d; i0 += 32) {
        int s = __ldg(&g_csr[base + i0 + lane]);
        #pragma unroll
        for (int j = 0; j < 32; j += 4) {
            int s0 = __shfl_sync(0xffffffffu, s, j + 0);
            int s1 = __shfl_sync(0xffffffffu, s, j + 1);
            int s2 = __shfl_sync(0xffffffffu, s, j + 2);
            int s3 = __shfl_sync(0xffffffffu, s, j + 3);
            a0 += __ldg(&h1[(size_t)s0 * H_DIM + lane]);
            a1 += __ldg(&h1[(size_t)s1 * H_DIM + lane]);
            a2 += __ldg(&h1[(size_t)s2 * H_DIM + lane]);
            a3 += __ldg(&h1[(size_t)s3 * H_DIM + lane]);
        }
    }
    if (i0 < d) {
        int m = d - i0;
        int s = (lane < m) ? __ldg(&g_csr[base + i0 + lane]) : 0;
        int j = 0;
        for (; j + 4 <= m; j += 4) {
            int s0 = __shfl_sync(0xffffffffu, s, j + 0);
            int s1 = __shfl_sync(0xffffffffu, s, j + 1);
            int s2 = __shfl_sync(0xffffffffu, s, j + 2);
            int s3 = __shfl_sync(0xffffffffu, s, j + 3);
            a0 += __ldg(&h1[(size_t)s0 * H_DIM + lane]);
            a1 += __ldg(&h1[(size_t)s1 * H_DIM + lane]);
            a2 += __ldg(&h1[(size_t)s2 * H_DIM + lane]);
            a3 += __ldg(&h1[(size_t)s3 * H_DIM + lane]);
        }
        for (; j < m; j++) {
            int s0 = __shfl_sync(0xffffffffu, s, j);
            a0 += __ldg(&h1[(size_t)s0 * H_DIM + lane]);
        }
    }
    float acc = (a0 + a1) + (a2 + a3);

    float di = rsqrtf((float)(d + 1));
    float tv = fmaf(di, acc, b1[lane]);
    tv = fmaxf(tv, 0.0f);
    float p0 = tv * W2[lane * 2 + 0];
    float p1 = tv * W2[lane * 2 + 1];
    #pragma unroll
    for (int o = 16; o > 0; o >>= 1) {
        p0 += __shfl_down_sync(0xffffffffu, p0, o);
        p1 += __shfl_down_sync(0xffffffffu, p1, o);
    }
    if (lane == 0)
        *(float2*)(g_gs + (size_t)w * 2) = make_float2(p0 * di, p1 * di);
}

// ---------------- fused L2 gather + log_softmax: thread per dst ----------------
__global__ void k_agg2_out(const float* __restrict__ b2, float* __restrict__ out, int n) {
    int i = blockIdx.x * blockDim.x + threadIdx.x;
    if (i >= n) return;
    const float2* gs2 = (const float2*)g_gs;
    int base = g_off[i];
    int d = g_degi[i];
    float2 a = gs2[i];                               // self-loop term
    int j = 0;
    for (; j + 4 <= d; j += 4) {
        int s0 = __ldg(&g_csr[base + j + 0]);
        int s1 = __ldg(&g_csr[base + j + 1]);
        int s2 = __ldg(&g_csr[base + j + 2]);
        int s3 = __ldg(&g_csr[base + j + 3]);
        float2 v0 = gs2[s0], v1 = gs2[s1], v2 = gs2[s2], v3 = gs2[s3];
        a.x += v0.x + v1.x + v2.x + v3.x;
        a.y += v0.y + v1.y + v2.y + v3.y;
    }
    for (; j < d; j++) {
        float2 v = gs2[__ldg(&g_csr[base + j])];
        a.x += v.x; a.y += v.y;
    }
    float di = rsqrtf((float)(d + 1));
    float l0 = fmaf(di, a.x, b2[0]);
    float l1 = fmaf(di, a.y, b2[1]);
    float m = fmaxf(l0, l1);
    float lse = m + log1pf(expf(fminf(l0, l1) - m));
    ((float2*)out)[i] = make_float2(l0 - lse, l1 - lse);
}

extern "C" void kernel_launch(void* const* d_in, const int* in_sizes, int n_in,
                              void* d_out, int out_size) {
    const float* x  = (const float*)d_in[0];      // [N,128] f32
    const int*   ei = (const int*)d_in[1];        // [2,E] int32
    const float* W1 = (const float*)d_in[2];      // [128,32]
    const float* b1 = (const float*)d_in[3];      // [32]
    const float* W2 = (const float*)d_in[4];      // [32,2]
    const float* b2 = (const float*)d_in[5];      // [2]
    float*       out = (float*)d_out;             // [N,2]

    const int N = in_sizes[0] / F_DIM;
    const int E = in_sizes[1] / 2;
    const int TB = 256;
    const int nb = (N + 1023) / 1024;

    // Lazy handle creation (host-side objects only; created on the un-captured
    // correctness call, reused identically on every subsequent/captured call)
    static cudaStream_t s1 = nullptr;
    static cudaEvent_t evA = nullptr, evB = nullptr;
    if (!s1) {
        cudaStreamCreateWithFlags(&s1, cudaStreamNonBlocking);
        cudaEventCreateWithFlags(&evA, cudaEventDisableTiming);
        cudaEventCreateWithFlags(&evB, cudaEventDisableTiming);
    }

    k_zero<<<(N + TB - 1) / TB, TB>>>(N);
    k_hist<<<(E + TB - 1) / TB, TB>>>(ei, E);
    cudaEventRecord(evA, 0);

    // Fork: GEMM1 only needs g_degi (hist); overlap it with scan+scatter
    cudaStreamWaitEvent(s1, evA, 0);
    k_gemm1<<<(N + 63) / 64, 128, 0, s1>>>(x, W1, N);
    cudaEventRecord(evB, s1);

    k_scan1  <<<nb, 1024>>>(N);
    k_scan2  <<<1, 1024>>>(nb);
    k_scan3  <<<(N + TB - 1) / TB, TB>>>(N);
    k_scatter<<<(E + TB - 1) / TB, TB>>>(ei, E);

    // Join: aggregation needs both CSR (stream 0) and h1s (s1)
    cudaStreamWaitEvent(0, evB, 0);
    k_agg1_l2 <<<(N * 32 + TB - 1) / TB, TB>>>(b1, W2, N);
    k_agg2_out<<<(N + TB - 1) / TB, TB>>>(b2, out, N);
}